// round 2
// baseline (speedup 1.0000x reference)
#include <cuda_runtime.h>

// NMS peak detection:
//   x: (8, 1, 1024, 1024) fp32
//   peak(p) <=> x[p] > 0.5 && no q in 51x51 window centered at p with x[q] > x[p]
//   output: (4096, 4) rows [n, c, h, w] in row-major (linear-index) order, -1 fill.
//   OUTPUT DTYPE: float32 (reference int32 indices are coerced to float by the pipeline;
//   writing int -1 produced 0xFFFFFFFF = NaN -> rel_err NaN last round).
//
// Stage 1: per 26x26 tile, find tile max; every element equal to tile max (and > 0.5)
//          is a candidate (any true peak must equal its tile max: all tile members lie
//          within L-inf distance 25, i.e. inside the 51x51 window).
// Stage 2: exact verification of candidates against the full clipped 51x51 window,
//          coalesced column-per-thread with block-wide early exit.
// Stage 3: rank peaks by linear index (O(n^2), n ~ 3400) to reproduce nonzero() order.

#define IMG_H 1024
#define IMG_W 1024
#define NIMG  8
#define RAD   25
#define TILE  26
#define NTX   40          // ceil(1024 / 26)
#define MAXD  4096
#define CAND_CAP (1 << 16)
#define PEAK_CAP 8192

__device__ int g_cand_count;
__device__ int g_cand[CAND_CAP];
__device__ int g_peak_count;
__device__ int g_peaks[PEAK_CAP];

__global__ void reset_kernel(float* __restrict__ out) {
    int i = blockIdx.x * blockDim.x + threadIdx.x;
    if (i < MAXD * 4) out[i] = -1.0f;
    if (i == 0) { g_cand_count = 0; g_peak_count = 0; }
}

// One block per 26x26 tile. 256 threads.
__global__ void cand_kernel(const float* __restrict__ x) {
    const int n  = blockIdx.z;
    const int h0 = blockIdx.y * TILE;
    const int w0 = blockIdx.x * TILE;
    const float* img = x + (size_t)n * IMG_H * IMG_W;

    __shared__ float smax[256];

    float m = -1.0f;
    #pragma unroll
    for (int i = threadIdx.x; i < TILE * TILE; i += 256) {
        int h = h0 + i / TILE;
        int w = w0 + i % TILE;
        if (h < IMG_H && w < IMG_W) m = fmaxf(m, __ldg(&img[h * IMG_W + w]));
    }
    smax[threadIdx.x] = m;
    __syncthreads();
    #pragma unroll
    for (int s = 128; s > 0; s >>= 1) {
        if (threadIdx.x < s)
            smax[threadIdx.x] = fmaxf(smax[threadIdx.x], smax[threadIdx.x + s]);
        __syncthreads();
    }
    const float tmax = smax[0];
    if (tmax <= 0.5f) return;

    // Collect every element equal to the tile max (handles exact-tie co-peaks).
    #pragma unroll
    for (int i = threadIdx.x; i < TILE * TILE; i += 256) {
        int h = h0 + i / TILE;
        int w = w0 + i % TILE;
        if (h < IMG_H && w < IMG_W) {
            float v = __ldg(&img[h * IMG_W + w]);
            if (v == tmax) {
                int slot = atomicAdd(&g_cand_count, 1);
                if (slot < CAND_CAP)
                    g_cand[slot] = n * (IMG_H * IMG_W) + h * IMG_W + w;
            }
        }
    }
}

// 64 threads per block; thread t covers window column t, loops over window rows.
// Block-wide early exit through a volatile shared flag.
__global__ void verify_kernel(const float* __restrict__ x) {
    volatile __shared__ int bad;
    const int ncand = min(g_cand_count, CAND_CAP);
    const int tid = threadIdx.x;

    for (int ci = blockIdx.x; ci < ncand; ci += gridDim.x) {
        const int lin = g_cand[ci];
        const int n   = lin / (IMG_H * IMG_W);
        const int rem = lin % (IMG_H * IMG_W);
        const int h   = rem / IMG_W;
        const int w   = rem % IMG_W;
        const float* img = x + (size_t)n * IMG_H * IMG_W;
        const float pv = __ldg(&img[rem]);

        if (tid == 0) bad = 0;
        __syncthreads();

        const int hlo = max(h - RAD, 0), hhi = min(h + RAD, IMG_H - 1);
        const int wlo = max(w - RAD, 0), whi = min(w + RAD, IMG_W - 1);
        const int nw  = whi - wlo + 1;

        if (tid < nw) {
            const float* col = img + wlo + tid;
            for (int hh = hlo; hh <= hhi; ++hh) {
                if (bad) break;
                if (__ldg(&col[hh * IMG_W]) > pv) { bad = 1; break; }
            }
        }
        __syncthreads();
        if (tid == 0 && !bad) {
            int slot = atomicAdd(&g_peak_count, 1);
            if (slot < PEAK_CAP) g_peaks[slot] = lin;
        }
        __syncthreads();
    }
}

// Rank each peak by its linear index (== jnp.nonzero row-major order), write rows.
__global__ void rank_kernel(float* __restrict__ out) {
    const int cnt = min(g_peak_count, PEAK_CAP);
    for (int i = blockIdx.x * blockDim.x + threadIdx.x; i < cnt;
         i += gridDim.x * blockDim.x) {
        const int lin = g_peaks[i];
        int rank = 0;
        for (int j = 0; j < cnt; ++j) rank += (g_peaks[j] < lin);
        if (rank < MAXD) {
            const int n   = lin / (IMG_H * IMG_W);
            const int rem = lin % (IMG_H * IMG_W);
            out[rank * 4 + 0] = (float)n;
            out[rank * 4 + 1] = 0.0f;
            out[rank * 4 + 2] = (float)(rem / IMG_W);
            out[rank * 4 + 3] = (float)(rem % IMG_W);
        }
    }
}

extern "C" void kernel_launch(void* const* d_in, const int* in_sizes, int n_in,
                              void* d_out, int out_size) {
    const float* x = (const float*)d_in[0];
    float* out = (float*)d_out;

    reset_kernel<<<(MAXD * 4 + 255) / 256, 256>>>(out);

    dim3 grid(NTX, NTX, NIMG);
    cand_kernel<<<grid, 256>>>(x);

    verify_kernel<<<4096, 64>>>(x);

    rank_kernel<<<16, 256>>>(out);
}

// round 3
// speedup vs baseline: 1.3288x; 1.3288x over previous
#include <cuda_runtime.h>

// NMS peak detection, exact:
//   x: (8, 1, 1024, 1024) fp32
//   peak(p) <=> x[p] > 0.5 && no q in 51x51 window with x[q] > x[p]
//   output (float32): (4096, 4) rows [n, c, h, w] in row-major linear-index order, -1 fill.
//
// Stage 1 (cand): per aligned 26x26 tile, compute tile max (stored to g_tilemax) and emit
//   every element equal to the tile max with value > 0.5 as a candidate. Any true peak
//   must equal its tile max (tile fits inside its own 51x51 window).
// Stage 2 (verify): for each candidate, its window is covered by <=16 aligned tiles.
//   Tiles with tilemax <= pv cannot hold a strictly greater element -> skipped for free.
//   Offending tiles get an exact warp-scan of window-tile intersection (ballot early exit).
// Stage 3 (rank): O(n^2) rank by linear index from SHARED memory -> nonzero() order.

#define IMG_H 1024
#define IMG_W 1024
#define NIMG  8
#define RAD   25
#define TILE  26
#define NTX   40          // ceil(1024 / 26)
#define MAXD  4096
#define CAND_CAP (1 << 15)
#define PEAK_CAP 8192

__device__ int   g_cand_count;
__device__ int   g_cand[CAND_CAP];
__device__ int   g_peak_count;
__device__ int   g_peaks[PEAK_CAP];
__device__ float g_tilemax[NIMG * NTX * NTX];

__global__ void reset_kernel(float* __restrict__ out) {
    int i = blockIdx.x * blockDim.x + threadIdx.x;
    if (i < MAXD * 4) out[i] = -1.0f;
    if (i == 0) { g_cand_count = 0; g_peak_count = 0; }
}

// One block (256 thr) per 26x26 tile. Single global read; tile cached in shared.
__global__ void cand_kernel(const float* __restrict__ x) {
    const int n  = blockIdx.z;
    const int ty = blockIdx.y;
    const int tx = blockIdx.x;
    const int h0 = ty * TILE;
    const int w0 = tx * TILE;
    const float* img = x + (size_t)n * IMG_H * IMG_W;

    __shared__ float tilev[TILE * TILE];
    __shared__ float wmax[8];

    const int tid  = threadIdx.x;
    const int lane = tid & 31;
    const int wid  = tid >> 5;

    float m = -1.0f;
    #pragma unroll
    for (int i = tid; i < TILE * TILE; i += 256) {
        const int h = h0 + i / TILE;
        const int w = w0 + i % TILE;
        float v = (h < IMG_H && w < IMG_W) ? __ldg(&img[h * IMG_W + w]) : -1.0f;
        tilev[i] = v;
        m = fmaxf(m, v);
    }
    #pragma unroll
    for (int off = 16; off; off >>= 1)
        m = fmaxf(m, __shfl_xor_sync(0xffffffffu, m, off));
    if (lane == 0) wmax[wid] = m;
    __syncthreads();
    if (wid == 0) {
        float t = (lane < 8) ? wmax[lane] : -1.0f;
        #pragma unroll
        for (int off = 4; off; off >>= 1)
            t = fmaxf(t, __shfl_xor_sync(0xffffffffu, t, off));
        if (lane == 0) {
            wmax[0] = t;
            g_tilemax[(n * NTX + ty) * NTX + tx] = t;
        }
    }
    __syncthreads();
    const float tmax = wmax[0];
    if (tmax <= 0.5f) return;

    // Emit every element equal to the tile max (preserves exact-tie co-peaks).
    #pragma unroll
    for (int i = tid; i < TILE * TILE; i += 256) {
        if (tilev[i] == tmax) {
            const int h = h0 + i / TILE;
            const int w = w0 + i % TILE;
            int slot = atomicAdd(&g_cand_count, 1);
            if (slot < CAND_CAP)
                g_cand[slot] = n * (IMG_H * IMG_W) + h * IMG_W + w;
        }
    }
}

// One warp per candidate. Tile-max pruning, exact intersection scan on offenders.
__global__ void verify_kernel(const float* __restrict__ x) {
    const int lane = threadIdx.x & 31;
    const int gw   = (blockIdx.x * blockDim.x + threadIdx.x) >> 5;
    const int nwarps = (gridDim.x * blockDim.x) >> 5;
    const int ncand  = min(g_cand_count, CAND_CAP);

    for (int ci = gw; ci < ncand; ci += nwarps) {
        const int lin = g_cand[ci];
        const int n   = lin / (IMG_H * IMG_W);
        const int rem = lin % (IMG_H * IMG_W);
        const int h   = rem / IMG_W;
        const int w   = rem % IMG_W;
        const float* img = x + (size_t)n * IMG_H * IMG_W;
        const float pv = __ldg(&img[rem]);

        const int hlo = max(h - RAD, 0), hhi = min(h + RAD, IMG_H - 1);
        const int wlo = max(w - RAD, 0), whi = min(w + RAD, IMG_W - 1);
        const int tylo = hlo / TILE, tyhi = hhi / TILE;
        const int txlo = wlo / TILE, txhi = whi / TILE;

        bool bad = false;
        for (int ty = tylo; ty <= tyhi && !bad; ++ty) {
            for (int tx = txlo; tx <= txhi && !bad; ++tx) {
                if (__ldg(&g_tilemax[(n * NTX + ty) * NTX + tx]) <= pv) continue;
                // exact scan of window ∩ tile
                const int rlo = max(hlo, ty * TILE), rhi = min(hhi, ty * TILE + TILE - 1);
                const int clo = max(wlo, tx * TILE), chi = min(whi, tx * TILE + TILE - 1);
                const int nc  = chi - clo + 1;
                const int tot = (rhi - rlo + 1) * nc;
                for (int base = 0; base < tot; base += 32) {
                    const int i = base + lane;
                    bool hit = false;
                    if (i < tot) {
                        const int r = rlo + i / nc;
                        const int c = clo + i % nc;
                        hit = __ldg(&img[r * IMG_W + c]) > pv;
                    }
                    if (__any_sync(0xffffffffu, hit)) { bad = true; break; }
                }
            }
        }
        if (!bad && lane == 0) {
            int slot = atomicAdd(&g_peak_count, 1);
            if (slot < PEAK_CAP) g_peaks[slot] = lin;
        }
    }
}

// Rank peaks by linear index from shared memory (broadcast LDS inner loop).
__global__ void rank_kernel(float* __restrict__ out) {
    __shared__ int sp[PEAK_CAP];
    const int cnt = min(g_peak_count, PEAK_CAP);
    for (int j = threadIdx.x; j < cnt; j += blockDim.x) sp[j] = g_peaks[j];
    __syncthreads();

    for (int i = blockIdx.x * blockDim.x + threadIdx.x; i < cnt;
         i += gridDim.x * blockDim.x) {
        const int lin = sp[i];
        int rank = 0;
        int j = 0;
        for (; j + 4 <= cnt; j += 4) {
            rank += (sp[j]     < lin);
            rank += (sp[j + 1] < lin);
            rank += (sp[j + 2] < lin);
            rank += (sp[j + 3] < lin);
        }
        for (; j < cnt; ++j) rank += (sp[j] < lin);
        if (rank < MAXD) {
            const int n   = lin / (IMG_H * IMG_W);
            const int rem = lin % (IMG_H * IMG_W);
            out[rank * 4 + 0] = (float)n;
            out[rank * 4 + 1] = 0.0f;
            out[rank * 4 + 2] = (float)(rem / IMG_W);
            out[rank * 4 + 3] = (float)(rem % IMG_W);
        }
    }
}

extern "C" void kernel_launch(void* const* d_in, const int* in_sizes, int n_in,
                              void* d_out, int out_size) {
    const float* x = (const float*)d_in[0];
    float* out = (float*)d_out;

    reset_kernel<<<(MAXD * 4 + 255) / 256, 256>>>(out);

    dim3 grid(NTX, NTX, NIMG);
    cand_kernel<<<grid, 256>>>(x);

    verify_kernel<<<200, 256>>>(x);   // 1600 warps, ~8 candidates each

    rank_kernel<<<16, 256>>>(out);
}

// round 4
// speedup vs baseline: 2.7411x; 2.0628x over previous
#include <cuda_runtime.h>

// NMS peak detection, exact:
//   x: (8, 1, 1024, 1024) fp32
//   peak(p) <=> x[p] > 0.5 && no q in 51x51 window with x[q] > x[p]
//   output (float32): (4096, 4) rows [n, c, h, w] in row-major linear-index order, -1 fill.
//
// Stage 1 (cand): per aligned 26x26 tile, tile max -> g_tilemax; elements equal to tile
//   max with value > 0.5 are candidates (any peak must equal its own tile max).
// Stage 2 (verify): window covers <=9 aligned tiles; lanes probe all tile maxes in
//   parallel, ballot -> offender mask; exact warp-scan of window∩tile only on offenders.
// Stage 3 (rank): warp-per-peak O(n^2/32) rank by linear index -> nonzero() order.

#define IMG_H 1024
#define IMG_W 1024
#define NIMG  8
#define RAD   25
#define TILE  26
#define NTX   40          // ceil(1024 / 26)
#define MAXD  4096
#define CAND_CAP (1 << 15)
#define PEAK_CAP 8192
#define FULL  0xffffffffu

__device__ int   g_cand_count;
__device__ int   g_cand[CAND_CAP];
__device__ int   g_peak_count;
__device__ int   g_peaks[PEAK_CAP];
__device__ float g_tilemax[NIMG * NTX * NTX];

__global__ void reset_kernel(float* __restrict__ out) {
    int i = blockIdx.x * blockDim.x + threadIdx.x;
    if (i < MAXD * 4) out[i] = -1.0f;
    if (i == 0) { g_cand_count = 0; g_peak_count = 0; }
}

// One block (256 thr) per 26x26 tile. Values held in registers; single global read.
__global__ void cand_kernel(const float* __restrict__ x) {
    const int n  = blockIdx.z;
    const int ty = blockIdx.y;
    const int tx = blockIdx.x;
    const int h0 = ty * TILE;
    const int w0 = tx * TILE;
    const float* img = x + ((size_t)n << 20);

    __shared__ float wmax[8];

    const int tid  = threadIdx.x;
    const int lane = tid & 31;
    const int wid  = tid >> 5;

    float v[3];
    float m = -1.0f;
    #pragma unroll
    for (int k = 0; k < 3; ++k) {
        const int i = tid + k * 256;
        v[k] = -1.0f;
        if (i < TILE * TILE) {
            const int h = h0 + i / TILE;
            const int w = w0 + i % TILE;
            if (h < IMG_H && w < IMG_W) v[k] = __ldg(&img[(h << 10) + w]);
        }
        m = fmaxf(m, v[k]);
    }
    #pragma unroll
    for (int off = 16; off; off >>= 1)
        m = fmaxf(m, __shfl_xor_sync(FULL, m, off));
    if (lane == 0) wmax[wid] = m;
    __syncthreads();
    if (wid == 0) {
        float t = (lane < 8) ? wmax[lane] : -1.0f;
        #pragma unroll
        for (int off = 4; off; off >>= 1)
            t = fmaxf(t, __shfl_xor_sync(FULL, t, off));
        if (lane == 0) {
            wmax[0] = t;
            g_tilemax[(n * NTX + ty) * NTX + tx] = t;
        }
    }
    __syncthreads();
    const float tmax = wmax[0];
    if (tmax <= 0.5f) return;

    #pragma unroll
    for (int k = 0; k < 3; ++k) {
        if (v[k] == tmax) {
            const int i = tid + k * 256;
            const int h = h0 + i / TILE;
            const int w = w0 + i % TILE;
            int slot = atomicAdd(&g_cand_count, 1);
            if (slot < CAND_CAP)
                g_cand[slot] = (n << 20) + (h << 10) + w;
        }
    }
}

// One warp per candidate. Lane-parallel tilemax probe, exact scan only on offenders.
__global__ void verify_kernel(const float* __restrict__ x) {
    const int lane   = threadIdx.x & 31;
    const int gw     = (blockIdx.x * blockDim.x + threadIdx.x) >> 5;
    const int nwarps = (gridDim.x * blockDim.x) >> 5;
    const int ncand  = min(g_cand_count, CAND_CAP);

    for (int ci = gw; ci < ncand; ci += nwarps) {
        const int lin = g_cand[ci];
        const int n   = lin >> 20;
        const int rem = lin & ((1 << 20) - 1);
        const int h   = rem >> 10;
        const int w   = rem & 1023;
        const float* img = x + ((size_t)n << 20);
        const float pv = __ldg(&img[rem]);

        const int hlo = max(h - RAD, 0), hhi = min(h + RAD, IMG_H - 1);
        const int wlo = max(w - RAD, 0), whi = min(w + RAD, IMG_W - 1);
        const int tylo = hlo / TILE, tyhi = hhi / TILE;
        const int txlo = wlo / TILE, txhi = whi / TILE;
        const int ntw  = txhi - txlo + 1;            // <= 3
        const int ntiles = (tyhi - tylo + 1) * ntw;  // <= 9

        // Parallel probe of all covering tile maxes (own tile: max == pv -> not offender).
        bool off = false;
        if (lane < ntiles) {
            const int tty = tylo + lane / ntw;
            const int ttx = txlo + lane % ntw;
            off = __ldg(&g_tilemax[(n * NTX + tty) * NTX + ttx]) > pv;
        }
        unsigned offmask = __ballot_sync(FULL, off);

        bool bad = false;
        while (offmask && !bad) {
            const int b = __ffs(offmask) - 1;
            offmask &= offmask - 1;
            const int tty = tylo + b / ntw;
            const int ttx = txlo + b % ntw;
            const int rlo = max(hlo, tty * TILE), rhi = min(hhi, tty * TILE + TILE - 1);
            const int clo = max(wlo, ttx * TILE), chi = min(whi, ttx * TILE + TILE - 1);
            const int nc  = chi - clo + 1;
            const int tot = (rhi - rlo + 1) * nc;
            for (int base = 0; base < tot; base += 32) {
                const int i = base + lane;
                bool hit = false;
                if (i < tot) {
                    const int r = rlo + i / nc;
                    const int c = clo + i % nc;
                    hit = __ldg(&img[(r << 10) + c]) > pv;
                }
                if (__any_sync(FULL, hit)) { bad = true; break; }
            }
        }
        if (!bad && lane == 0) {
            int slot = atomicAdd(&g_peak_count, 1);
            if (slot < PEAK_CAP) g_peaks[slot] = lin;
        }
    }
}

// Warp-per-peak rank: lanes split the scan 32 ways, shuffle-reduce, float4 row store.
__global__ void rank_kernel(float* __restrict__ out) {
    __shared__ int sp[PEAK_CAP];
    const int cnt = min(g_peak_count, PEAK_CAP);
    for (int j = threadIdx.x; j < cnt; j += blockDim.x) sp[j] = g_peaks[j];
    __syncthreads();

    const int lane = threadIdx.x & 31;
    const int gw   = (blockIdx.x * blockDim.x + threadIdx.x) >> 5;
    const int nw   = (gridDim.x * blockDim.x) >> 5;

    for (int i = gw; i < cnt; i += nw) {
        const int lin = sp[i];
        int r = 0;
        for (int j = lane; j < cnt; j += 32) r += (sp[j] < lin);
        #pragma unroll
        for (int off = 16; off; off >>= 1)
            r += __shfl_xor_sync(FULL, r, off);
        if (lane == 0 && r < MAXD) {
            const int n   = lin >> 20;
            const int rem = lin & ((1 << 20) - 1);
            float4 row = make_float4((float)n, 0.0f,
                                     (float)(rem >> 10), (float)(rem & 1023));
            reinterpret_cast<float4*>(out)[r] = row;
        }
    }
}

extern "C" void kernel_launch(void* const* d_in, const int* in_sizes, int n_in,
                              void* d_out, int out_size) {
    const float* x = (const float*)d_in[0];
    float* out = (float*)d_out;

    reset_kernel<<<(MAXD * 4 + 255) / 256, 256>>>(out);

    dim3 grid(NTX, NTX, NIMG);
    cand_kernel<<<grid, 256>>>(x);

    verify_kernel<<<1600, 256>>>(x);   // 12800 warps: ~1 candidate each

    rank_kernel<<<512, 256>>>(out);
}